// round 9
// baseline (speedup 1.0000x reference)
#include <cuda_runtime.h>

// 2-layer LSTM (H=50), T=65536 serial steps, one persistent CTA, 416 threads.
// Split-dot quad layout: lane l of warp w (13 warps) owns
//   half = l>>4      (which half of every 50-dim dot: dims 0..27 / 28..55pad)
//   k    = (l>>2)&3  (gate kind i/f/g/o)
//   j0   = l&3       (unit-within-warp; unit u = 4w + j0, 52 slots >= 50)
// Each lane computes HALF of its gate row's dots (depth-7 FFMA2 chains);
// one shfl.xor(16)+add completes the dot; the 4 gates of a unit are then
// gathered with 4 intra-warp index shuffles and the cell state is updated
// redundantly in all 8 lanes of the unit. 2 barriers/step. More warps
// (3.25/SMSP vs 2) hide LDS/MUFU/SHFL latency; total instr count unchanged.

#define HDIM     50
#define INP      8
#define CHUNK    1024
#define NTHREADS 416

typedef unsigned long long u64;

__device__ __forceinline__ u64 pk2(float lo, float hi) {
    u64 r; asm("mov.b64 %0, {%1,%2};" : "=l"(r) : "f"(lo), "f"(hi)); return r;
}
__device__ __forceinline__ float2 upk2(u64 v) {
    float2 f; asm("mov.b64 {%0,%1}, %2;" : "=f"(f.x), "=f"(f.y) : "l"(v)); return f;
}
__device__ __forceinline__ u64 ffma2(u64 a, u64 b, u64 c) {
    u64 d; asm("fma.rn.f32x2 %0, %1, %2, %3;" : "=l"(d) : "l"(a), "l"(b), "l"(c)); return d;
}
__device__ __forceinline__ u64 add2(u64 a, u64 b) {
    u64 d; asm("add.rn.f32x2 %0, %1, %2;" : "=l"(d) : "l"(a), "l"(b)); return d;
}
__device__ __forceinline__ float tanha(float x) {
    float r; asm("tanh.approx.f32 %0, %1;" : "=f"(r) : "f"(x)); return r;
}

__global__ __launch_bounds__(NTHREADS, 1)
void lstm_r9_kernel(const float* __restrict__ input_seq,
                    const float* __restrict__ W_ih1, const float* __restrict__ W_hh1,
                    const float* __restrict__ b_ih1, const float* __restrict__ b_hh1,
                    const float* __restrict__ W_ih2, const float* __restrict__ W_hh2,
                    const float* __restrict__ b_ih2, const float* __restrict__ b_hh2,
                    const float* __restrict__ W_out, const float* __restrict__ b_out,
                    float* __restrict__ out, int T)
{
    __shared__ __align__(16) float sh1[56];    // h1(s), [50..55]=0
    __shared__ __align__(16) float sh2[56];    // h2(s), [50..55]=0
    __shared__ __align__(16) float swout[56];  // W_out padded
    __shared__ __align__(16) float xbuf[(CHUNK + 1) * INP];

    const int t = threadIdx.x;
    const int w = t >> 5;
    const int l = t & 31;
    const int half = (l >> 4) & 1;        // dot half
    const int k = (l >> 2) & 3;           // gate kind: 0=i 1=f 2=g 3=o
    const int j0 = l & 3;                 // unit-within-warp
    const int uraw = w * 4 + j0;          // 0..51
    const bool uvalid = (uraw < HDIM);
    const int u = uvalid ? uraw : (HDIM - 1);
    const int row = k * HDIM + u;
    const int qb = (l & 16) + j0;         // quad-gather base lane

    // activation: act(x) = fmaf(tanha(K*x), K, A); K folded into weights
    const float actK = (k == 2) ? 1.0f : 0.5f;
    const float actA = (k == 2) ? 0.0f : 0.5f;

    // ---- per-thread HALF-row weights, pre-scaled by actK.
    // pair j covers dims d0=2*(14*half+j), d1=d0+1 of the 56-padded h vector.
    u64 wx[3], wh1[14], wi2[14], wh2[14];
    float w6x, w7K, bb1K, bb2K;
    {
        const float* r2 = W_hh1 + row * HDIM;
        const float* r3 = W_ih2 + row * HDIM;
        const float* r4 = W_hh2 + row * HDIM;
        const int pb = half * 14;
        #pragma unroll
        for (int j = 0; j < 14; ++j) {
            int d0 = 2 * (pb + j), d1 = d0 + 1;
            float e0 = (d0 < HDIM) ? actK : 0.0f;
            float e1 = (d1 < HDIM) ? actK : 0.0f;
            float v20 = (d0 < HDIM) ? r2[d0] : 0.0f;
            float v21 = (d1 < HDIM) ? r2[d1] : 0.0f;
            float v30 = (d0 < HDIM) ? r3[d0] : 0.0f;
            float v31 = (d1 < HDIM) ? r3[d1] : 0.0f;
            float v40 = (d0 < HDIM) ? r4[d0] : 0.0f;
            float v41 = (d1 < HDIM) ? r4[d1] : 0.0f;
            wh1[j] = pk2(e0 * v20, e1 * v21);
            wi2[j] = pk2(e0 * v30, e1 * v31);
            wh2[j] = pk2(e0 * v40, e1 * v41);
        }
        const float* r1 = W_ih1 + row * INP;
        const float hx = (half == 0) ? actK : 0.0f;   // x-dot in half A only
        wx[0] = pk2(hx * r1[0], hx * r1[1]);
        wx[1] = pk2(hx * r1[2], hx * r1[3]);
        wx[2] = pk2(hx * r1[4], hx * r1[5]);
        w6x = hx * r1[6];
        w7K = actK * r1[7];                            // post-reduction use
        bb1K = actK * (b_ih1[row] + b_hh1[row]);       // post-reduction add
        bb2K = actK * (b_ih2[row] + b_hh2[row]);
    }
    const float bo = b_out[0];
    if (t < 56) {
        swout[t] = (t < HDIM) ? W_out[t] : 0.0f;
        sh1[t] = 0.0f;
        sh2[t] = 0.0f;
    }

    float c1 = 0.0f, c2 = 0.0f, err = 0.0f, a1p = 0.0f;
    float x7_use = 0.0f, x7_next = 0.0f;
    __syncthreads();

    #pragma unroll 1
    for (int s = 0; s < T; ++s) {
        const int lo = s & (CHUNK - 1);
        if (lo == 0) {
            // old xbuf fully consumed at BAR_B of step s-1
            const float4* src = (const float4*)(input_seq + (size_t)s * INP);
            float4* dst = (float4*)xbuf;
            int n4 = (CHUNK + 1) * 2;
            int rem4 = (T - s) * 2;
            if (rem4 < n4) n4 = rem4;
            for (int i = t; i < n4; i += NTHREADS) dst[i] = src[i];
            __syncthreads();
            if (s == 0) {
                // bootstrap a1p(0) = bb1K + K*W_ih1@x(0)[0..6] (h1(-1)=0)
                float4 xa = *(const float4*)(xbuf);
                float4 xb = *(const float4*)(xbuf + 4);
                u64 a0 = ffma2(wx[0], pk2(xa.x, xa.y), pk2(w6x * xb.z, 0.0f));
                a0 = ffma2(wx[1], pk2(xa.z, xa.w), a0);
                a0 = ffma2(wx[2], pk2(xb.x, xb.y), a0);
                float2 f = upk2(a0);
                float ah = f.x + f.y;
                ah += __shfl_xor_sync(0xffffffffu, ah, 16);
                a1p = ah + bb1K;
                x7_next = xb.w;
            }
        }

        // ================= Phase A =================
        // x(s+1) loads + x-dot seed (off-path, carried into Phase B)
        const float* xn = &xbuf[(lo + 1) * INP];
        float4 xa = *(const float4*)(xn);
        float4 xb = *(const float4*)(xn + 4);
        u64 a0 = ffma2(wx[0], pk2(xa.x, xa.y), pk2(w6x * xb.z, 0.0f));
        a0 = ffma2(wx[1], pk2(xa.z, xa.w), a0);
        a0 = ffma2(wx[2], pk2(xb.x, xb.y), a0);
        u64 a1 = pk2(0.0f, 0.0f);

        // half-pass over sh2 feeds y-half-dot AND W_hh2-half @ h2(s-1)
        u64 y0 = pk2(0.0f, 0.0f), y1 = y0;
        u64 q0 = y0, q1 = y0;
        {
            const float4* hv = ((const float4*)sh2) + half * 7;
            const float4* wv = ((const float4*)swout) + half * 7;
            #pragma unroll
            for (int j = 0; j < 7; ++j) {
                float4 h = hv[j];
                float4 wq = wv[j];
                u64 hl = pk2(h.x, h.y), hh = pk2(h.z, h.w);
                y0 = ffma2(pk2(wq.x, wq.y), hl, y0);
                y1 = ffma2(pk2(wq.z, wq.w), hh, y1);
                q0 = ffma2(wh2[2*j],     hl, q0);
                q1 = ffma2(wh2[2*j + 1], hh, q1);
            }
        }
        // y reduce, err, gates1, cell1
        {
            float2 yf = upk2(add2(y0, y1));
            float yh = yf.x + yf.y;
            yh += __shfl_xor_sync(0xffffffffu, yh, 16);
            float y = yh + bo;                                  // y(s-1)
            err = (s != 0) ? fmaf(0.1f, x7_use - y, 0.9f * err) : 0.0f;
            if (t == 0 && s != 0) out[s - 1] = y;
            float g1K = fmaf(w7K, err, a1p);
            float v0 = fmaf(tanha(g1K), actK, actA);
            float I = __shfl_sync(0xffffffffu, v0, qb);
            float F = __shfl_sync(0xffffffffu, v0, qb + 4);
            float G = __shfl_sync(0xffffffffu, v0, qb + 8);
            float O = __shfl_sync(0xffffffffu, v0, qb + 12);
            c1 = fmaf(F, c1, I * G);
            float h1v = O * tanha(c1);
            if (l < 4 && uvalid) sh1[u] = h1v;   // k==0 && half==0
        }
        __syncthreads();   // BAR_A: h1(s) ready

        // ================= Phase B =================
        // half-pass over sh1 feeds W_ih2-half (gates2) AND W_hh1-half (a1p)
        u64 r0 = pk2(0.0f, 0.0f), r1 = r0;
        {
            const float4* hv = ((const float4*)sh1) + half * 7;
            #pragma unroll
            for (int j = 0; j < 7; ++j) {
                float4 h = hv[j];
                u64 hl = pk2(h.x, h.y), hh = pk2(h.z, h.w);
                r0 = ffma2(wi2[2*j],     hl, r0);
                r1 = ffma2(wi2[2*j + 1], hh, r1);
                a0 = ffma2(wh1[2*j],     hl, a0);
                a1 = ffma2(wh1[2*j + 1], hh, a1);
            }
        }
        {
            // gates2: (q + r) reduce across halves, + bb2K once
            float2 mf = upk2(add2(add2(q0, q1), add2(r0, r1)));
            float g2h = mf.x + mf.y;
            g2h += __shfl_xor_sync(0xffffffffu, g2h, 16);
            float g2K = g2h + bb2K;
            // a1p(s+1): reduce across halves, + bb1K once
            float2 af = upk2(add2(a0, a1));
            float ah = af.x + af.y;
            ah += __shfl_xor_sync(0xffffffffu, ah, 16);
            a1p = ah + bb1K;
            float v0 = fmaf(tanha(g2K), actK, actA);
            float I = __shfl_sync(0xffffffffu, v0, qb);
            float F = __shfl_sync(0xffffffffu, v0, qb + 4);
            float G = __shfl_sync(0xffffffffu, v0, qb + 8);
            float O = __shfl_sync(0xffffffffu, v0, qb + 12);
            c2 = fmaf(F, c2, I * G);
            float h2v = O * tanha(c2);
            if (l < 4 && uvalid) sh2[u] = h2v;   // k==0 && half==0
        }
        x7_use = x7_next;          // becomes x(s)[7] for Phase A(s+1)
        x7_next = xb.w;            // x(s+1)[7]
        __syncthreads();   // BAR_B: h2(s) ready
    }

    // epilogue: y(T-1) from final h2
    if (t == 0) {
        float y = bo;
        for (int j = 0; j < HDIM; ++j) y += swout[j] * sh2[j];
        out[T - 1] = y;
    }
}

extern "C" void kernel_launch(void* const* d_in, const int* in_sizes, int n_in,
                              void* d_out, int out_size) {
    const int T = in_sizes[0] / INP;
    lstm_r9_kernel<<<1, NTHREADS>>>(
        (const float*)d_in[0],
        (const float*)d_in[1], (const float*)d_in[2],
        (const float*)d_in[3], (const float*)d_in[4],
        (const float*)d_in[5], (const float*)d_in[6],
        (const float*)d_in[7], (const float*)d_in[8],
        (const float*)d_in[9], (const float*)d_in[10],
        (float*)d_out, T);
}